// round 5
// baseline (speedup 1.0000x reference)
#include <cuda_runtime.h>
#include <cuda_fp16.h>
#include <cstdint>
#include <cstddef>

// Sizes: hidden (2,4096,2048) f32; Win (6144,2048); conv_w (2048,1,3); Wout (2048,2048)
#define MDIM 8192
#define KDIM 2048
#define N1   6144
#define SEQMASK 4095
#define KT 32                    // 2048 / 64 k-tiles

// ---------------- device scratch ----------------
__device__ __half g_A [MDIM * KDIM];        // 32 MB
__device__ __half g_W1[N1   * KDIM];        // 24 MB
__device__ __half g_W2[KDIM * KDIM];        // 8 MB
__device__ __half g_y [MDIM * KDIM];        // 32 MB
__device__ float  g_BCx[(size_t)MDIM * N1]; // 192 MB

// ---------------- helpers ----------------
__device__ __forceinline__ uint32_t smem_u32(const void* p) {
    uint32_t a;
    asm("{ .reg .u64 t; cvta.to.shared.u64 t, %1; cvt.u32.u64 %0, t; }" : "=r"(a) : "l"(p));
    return a;
}
__device__ __forceinline__ void cp16(uint32_t dst, const void* src) {
    asm volatile("cp.async.cg.shared.global [%0], [%1], 16;" :: "r"(dst), "l"(src));
}
__device__ __forceinline__ void ldsm_x4(uint32_t& r0, uint32_t& r1, uint32_t& r2, uint32_t& r3, uint32_t addr) {
    asm volatile("ldmatrix.sync.aligned.m8n8.x4.shared.b16 {%0,%1,%2,%3}, [%4];"
                 : "=r"(r0), "=r"(r1), "=r"(r2), "=r"(r3) : "r"(addr));
}
__device__ __forceinline__ void mma16816(float* d, const uint32_t* a, const uint32_t* b) {
    asm volatile(
        "mma.sync.aligned.m16n8k16.row.col.f32.f16.f16.f32 "
        "{%0,%1,%2,%3}, {%4,%5,%6,%7}, {%8,%9}, {%0,%1,%2,%3};"
        : "+f"(d[0]), "+f"(d[1]), "+f"(d[2]), "+f"(d[3])
        : "r"(a[0]), "r"(a[1]), "r"(a[2]), "r"(a[3]), "r"(b[0]), "r"(b[1]));
}

#define SWZ(o) ((o) ^ (((o) >> 3) & 0x70))

// ---------------- f32 -> f16 convert ----------------
__global__ void __launch_bounds__(256) convert_kernel(const float4* __restrict__ src,
                                                      uint2* __restrict__ dst) {
    int i = blockIdx.x * 256 + threadIdx.x;
    float4 v = src[i];
    __half2 a = __floats2half2_rn(v.x, v.y);
    __half2 b = __floats2half2_rn(v.z, v.w);
    uint2 u;
    u.x = *reinterpret_cast<unsigned*>(&a);
    u.y = *reinterpret_cast<unsigned*>(&b);
    dst[i] = u;
}

// ---------------- TN fp16 GEMM: C[M,N] = A[M,K] * W[N,K]^T, fp32 out ----------------
// BM=BN=128, BK=64 halfs (128B SW128 rows), 3 stages, 512 threads (16 warps 4m x 4n),
// warp tile 32x32. 2 CTAs/SM (96KB smem, ~70 regs).
#define STAGE_BYTES 32768          // A 16KB + B 16KB
#define GSMEM (3 * STAGE_BYTES)    // 98304

__global__ void __launch_bounds__(512, 2) hgemm_tn(const __half* __restrict__ A,
                                                   const __half* __restrict__ W,
                                                   float* __restrict__ C, int ldc) {
    extern __shared__ char smem[];
    const int t = threadIdx.x;
    const int tm = blockIdx.y * 128;
    const int tn = blockIdx.x * 128;
    const uint32_t sb = smem_u32(smem);

    auto load_stage = [&](int st, int kt) {
        const uint32_t sa = sb + st * STAGE_BYTES;
        const __half* Ag = A + (size_t)tm * KDIM + kt * 64;
        const __half* Wg = W + (size_t)tn * KDIM + kt * 64;
        #pragma unroll
        for (int p = 0; p < 2; p++) {
            int id = p * 512 + t;
            int r = id >> 3, c = id & 7;
            cp16(sa + SWZ(r * 128 + c * 16), Ag + (size_t)r * KDIM + c * 8);
            cp16(sa + 16384 + SWZ(r * 128 + c * 16), Wg + (size_t)r * KDIM + c * 8);
        }
    };

    load_stage(0, 0); asm volatile("cp.async.commit_group;" ::: "memory");
    load_stage(1, 1); asm volatile("cp.async.commit_group;" ::: "memory");

    const int warp = t >> 5, lane = t & 31;
    const int wm = (warp >> 2) * 32;   // 4 warps in m
    const int wn = (warp & 3) * 32;    // 4 warps in n

    // A ldmatrix.x4 lane mapping: mat0 rows0-7/k0, mat1 rows8-15/k0, mat2 rows0-7/k16B, mat3 rows8-15/k16B
    const int g = lane >> 3;
    const int a_row = (g & 1) * 8 + (lane & 7);
    const int a_kb  = (g >> 1) * 16;
    // B ldmatrix.x4 lane mapping: mat0 n0-7/k0, mat1 n0-7/k16B, mat2 n8-15/k0, mat3 n8-15/k16B
    const int b_row = (lane >> 4) * 8 + (lane & 7);
    const int b_kb  = ((lane >> 3) & 1) * 16;

    const int axor = (a_row & 7) << 4;
    const int bxor = (b_row & 7) << 4;
    int rowA[2], rowB[2];
    #pragma unroll
    for (int mt = 0; mt < 2; mt++) rowA[mt] = (wm + mt * 16 + a_row) * 128;
    #pragma unroll
    for (int nb = 0; nb < 2; nb++) rowB[nb] = (wn + nb * 16 + b_row) * 128 + 16384;

    float acc[8][4] = {};   // [mt*4+nt]

    for (int kt = 0; kt < KT; kt++) {
        asm volatile("cp.async.wait_group 1;" ::: "memory");
        __syncthreads();
        if (kt + 2 < KT) load_stage((kt + 2) % 3, kt + 2);
        asm volatile("cp.async.commit_group;" ::: "memory");

        const uint32_t sc = sb + (kt % 3) * STAGE_BYTES;
        #pragma unroll
        for (int ks = 0; ks < 4; ks++) {
            const int ca = (ks * 32 + a_kb) ^ axor;
            const int cb = (ks * 32 + b_kb) ^ bxor;
            uint32_t fa[2][4], fb[4][2];
            #pragma unroll
            for (int mt = 0; mt < 2; mt++)
                ldsm_x4(fa[mt][0], fa[mt][1], fa[mt][2], fa[mt][3], sc + rowA[mt] + ca);
            #pragma unroll
            for (int nb = 0; nb < 2; nb++) {
                uint32_t r0, r1, r2, r3;
                ldsm_x4(r0, r1, r2, r3, sc + rowB[nb] + cb);
                fb[nb * 2][0] = r0; fb[nb * 2][1] = r1;
                fb[nb * 2 + 1][0] = r2; fb[nb * 2 + 1][1] = r3;
            }
            #pragma unroll
            for (int mt = 0; mt < 2; mt++)
                #pragma unroll
                for (int nt = 0; nt < 4; nt++)
                    mma16816(acc[mt * 4 + nt], fa[mt], fb[nt]);
        }
    }

    // epilogue
    #pragma unroll
    for (int mt = 0; mt < 2; mt++) {
        #pragma unroll
        for (int nt = 0; nt < 4; nt++) {
            const float* d = acc[mt * 4 + nt];
            int row = tm + wm + mt * 16 + (lane >> 2);
            int col = tn + wn + nt * 8 + (lane & 3) * 2;
            *reinterpret_cast<float2*>(C + (size_t)row * ldc + col)       = make_float2(d[0], d[1]);
            *reinterpret_cast<float2*>(C + (size_t)(row + 8) * ldc + col) = make_float2(d[2], d[3]);
        }
    }
}

// ---------------- fused B*x -> causal conv(L=3) -> *C, fp16 out ----------------
__global__ void __launch_bounds__(256) shortconv_kernel(const float* __restrict__ BCx,
                                                        const float* __restrict__ cw,
                                                        __half* __restrict__ y) {
    int gid = blockIdx.x * 256 + threadIdx.x;
    int m = gid >> 9;
    int h = (gid & 511) * 4;
    int s = m & SEQMASK;

    const float* row0 = BCx + (size_t)m * N1;
    float4 B0 = *reinterpret_cast<const float4*>(row0 + h);
    float4 Cc = *reinterpret_cast<const float4*>(row0 + 2048 + h);
    float4 X0 = *reinterpret_cast<const float4*>(row0 + 4096 + h);
    float4 B1 = make_float4(0.f, 0.f, 0.f, 0.f), X1 = B1, B2 = B1, X2 = B1;
    if (s >= 1) {
        const float* r1 = row0 - N1;
        B1 = *reinterpret_cast<const float4*>(r1 + h);
        X1 = *reinterpret_cast<const float4*>(r1 + 4096 + h);
    }
    if (s >= 2) {
        const float* r2 = row0 - 2 * N1;
        B2 = *reinterpret_cast<const float4*>(r2 + h);
        X2 = *reinterpret_cast<const float4*>(r2 + 4096 + h);
    }

    const float* b0 = (const float*)&B0; const float* b1 = (const float*)&B1;
    const float* b2 = (const float*)&B2; const float* x0 = (const float*)&X0;
    const float* x1 = (const float*)&X1; const float* x2 = (const float*)&X2;
    const float* cc = (const float*)&Cc;

    float out[4];
    #pragma unroll
    for (int j = 0; j < 4; j++) {
        float w0 = cw[(h + j) * 3 + 0];
        float w1 = cw[(h + j) * 3 + 1];
        float w2 = cw[(h + j) * 3 + 2];
        out[j] = cc[j] * (w0 * b2[j] * x2[j] + w1 * b1[j] * x1[j] + w2 * b0[j] * x0[j]);
    }
    __half2 h0 = __floats2half2_rn(out[0], out[1]);
    __half2 h1 = __floats2half2_rn(out[2], out[3]);
    *reinterpret_cast<__half2*>(y + (size_t)m * KDIM + h)     = h0;
    *reinterpret_cast<__half2*>(y + (size_t)m * KDIM + h + 2) = h1;
}

// ---------------- launch ----------------
extern "C" void kernel_launch(void* const* d_in, const int* in_sizes, int n_in,
                              void* d_out, int out_size) {
    const float* hs   = (const float*)d_in[0];
    const float* Win  = (const float*)d_in[1];
    const float* cw   = (const float*)d_in[2];
    const float* Wout = (const float*)d_in[3];
    float* out = (float*)d_out;

    void *pA, *pW1, *pW2, *pY, *pBCx;
    cudaGetSymbolAddress(&pA,  g_A);
    cudaGetSymbolAddress(&pW1, g_W1);
    cudaGetSymbolAddress(&pW2, g_W2);
    cudaGetSymbolAddress(&pY,  g_y);
    cudaGetSymbolAddress(&pBCx, g_BCx);

    cudaFuncSetAttribute(hgemm_tn, cudaFuncAttributeMaxDynamicSharedMemorySize, GSMEM);

    convert_kernel<<<16384, 256>>>((const float4*)hs,   (uint2*)pA);
    convert_kernel<<<12288, 256>>>((const float4*)Win,  (uint2*)pW1);
    convert_kernel<<<4096,  256>>>((const float4*)Wout, (uint2*)pW2);

    // GEMM1: BCx[8192,6144] = A * Win^T
    hgemm_tn<<<dim3(N1 / 128, MDIM / 128), 512, GSMEM>>>(
        (const __half*)pA, (const __half*)pW1, (float*)pBCx, N1);

    shortconv_kernel<<<(MDIM * KDIM / 4) / 256, 256>>>((const float*)pBCx, cw, (__half*)pY);

    // GEMM2: out[8192,2048] = y * Wout^T
    hgemm_tn<<<dim3(KDIM / 128, MDIM / 128), 512, GSMEM>>>(
        (const __half*)pY, (const __half*)pW2, out, KDIM);
}

// round 6
// speedup vs baseline: 1.5737x; 1.5737x over previous
#include <cuda_runtime.h>
#include <cuda_fp16.h>
#include <cstdint>
#include <cstddef>

// Sizes: hidden (2,4096,2048) f32; Win (6144,2048); conv_w (2048,1,3); Wout (2048,2048)
#define MDIM 8192
#define KDIM 2048
#define N1   6144
#define SEQMASK 4095
#define KT 32

// ---------------- device scratch ----------------
__device__ __half g_A  [MDIM * KDIM];          // 32 MB
__device__ __half g_W1 [N1   * KDIM];          // 24 MB
__device__ __half g_W2 [KDIM * KDIM];          // 8 MB
__device__ __half g_y  [MDIM * KDIM];          // 32 MB
__device__ __half g_BCx[(size_t)MDIM * N1];    // 96 MB fp16 GEMM1 output

// ---------------- helpers ----------------
__device__ __forceinline__ uint32_t smem_u32(const void* p) {
    uint32_t a;
    asm("{ .reg .u64 t; cvta.to.shared.u64 t, %1; cvt.u32.u64 %0, t; }" : "=r"(a) : "l"(p));
    return a;
}
__device__ __forceinline__ void cp16(uint32_t dst, const void* src) {
    asm volatile("cp.async.cg.shared.global [%0], [%1], 16;" :: "r"(dst), "l"(src));
}
__device__ __forceinline__ void ldsm_x4(uint32_t& r0, uint32_t& r1, uint32_t& r2, uint32_t& r3, uint32_t addr) {
    asm volatile("ldmatrix.sync.aligned.m8n8.x4.shared.b16 {%0,%1,%2,%3}, [%4];"
                 : "=r"(r0), "=r"(r1), "=r"(r2), "=r"(r3) : "r"(addr));
}
__device__ __forceinline__ void ldsm_x2(uint32_t& r0, uint32_t& r1, uint32_t addr) {
    asm volatile("ldmatrix.sync.aligned.m8n8.x2.shared.b16 {%0,%1}, [%2];"
                 : "=r"(r0), "=r"(r1) : "r"(addr));
}
__device__ __forceinline__ void mma16816(float* d, const uint32_t* a, const uint32_t* b) {
    asm volatile(
        "mma.sync.aligned.m16n8k16.row.col.f32.f16.f16.f32 "
        "{%0,%1,%2,%3}, {%4,%5,%6,%7}, {%8,%9}, {%0,%1,%2,%3};"
        : "+f"(d[0]), "+f"(d[1]), "+f"(d[2]), "+f"(d[3])
        : "r"(a[0]), "r"(a[1]), "r"(a[2]), "r"(a[3]), "r"(b[0]), "r"(b[1]));
}

#define SWZ(o) ((o) ^ (((o) >> 3) & 0x70))

// ---------------- f32 -> f16 convert ----------------
__global__ void __launch_bounds__(256) convert_kernel(const float4* __restrict__ src,
                                                      uint2* __restrict__ dst) {
    int i = blockIdx.x * 256 + threadIdx.x;
    float4 v = src[i];
    __half2 a = __floats2half2_rn(v.x, v.y);
    __half2 b = __floats2half2_rn(v.z, v.w);
    uint2 u;
    u.x = *reinterpret_cast<unsigned*>(&a);
    u.y = *reinterpret_cast<unsigned*>(&b);
    dst[i] = u;
}

// ---------------- TN fp16 GEMM (R2-proven config): C[M,N] = A[M,K] * W[N,K]^T ----------
// BM=BN=128, BK=64 halfs (128B SW128 rows), 3 stages, 256 threads (8 warps 2m x 4n),
// warp tile 64x32 = 4x4 m16n8k16 frags. OutT selects fp16 or fp32 epilogue.
template <typename OutT>
__global__ void __launch_bounds__(256, 1) hgemm_tn(const __half* __restrict__ A,
                                                   const __half* __restrict__ W,
                                                   OutT* __restrict__ C, int ldc) {
    extern __shared__ char smem[];
    const int t = threadIdx.x;
    const int tm = blockIdx.y * 128;
    const int tn = blockIdx.x * 128;

    const uint32_t sbase = smem_u32(smem);
    const uint32_t saA = sbase;
    const uint32_t saB = sbase + 3 * 16384;

    auto load_stage = [&](int st, int kt) {
        const __half* Ag = A + (size_t)tm * KDIM + kt * 64;
        const __half* Wg = W + (size_t)tn * KDIM + kt * 64;
        #pragma unroll
        for (int p = 0; p < 4; p++) {
            int id = p * 256 + t;
            int r = id >> 3, c = id & 7;
            cp16(saA + st * 16384 + SWZ(r * 128 + c * 16), Ag + (size_t)r * KDIM + c * 8);
            cp16(saB + st * 16384 + SWZ(r * 128 + c * 16), Wg + (size_t)r * KDIM + c * 8);
        }
    };

    float acc[16][4] = {};

    load_stage(0, 0);
    asm volatile("cp.async.commit_group;" ::: "memory");
    load_stage(1, 1);
    asm volatile("cp.async.commit_group;" ::: "memory");

    const int warp = t >> 5, lane = t & 31;
    const int wm = (warp >> 2) * 64;
    const int wn = (warp & 3) * 32;
    const int g = lane >> 3;
    const int a_row = (g & 1) * 8 + (lane & 7);
    const int a_kb  = (g >> 1) * 16;
    const int lg = lane & 15;
    const int b_row = lg & 7;
    const int b_kb  = (lg >> 3) * 16;

    for (int kt = 0; kt < KT; kt++) {
        asm volatile("cp.async.wait_group 1;" ::: "memory");
        __syncthreads();
        if (kt + 2 < KT) load_stage((kt + 2) % 3, kt + 2);
        asm volatile("cp.async.commit_group;" ::: "memory");

        const int st = kt % 3;
        const uint32_t aT = saA + st * 16384;
        const uint32_t bT = saB + st * 16384;
        #pragma unroll
        for (int ks = 0; ks < 4; ks++) {
            uint32_t a[4][4], b[4][2];
            #pragma unroll
            for (int mt = 0; mt < 4; mt++)
                ldsm_x4(a[mt][0], a[mt][1], a[mt][2], a[mt][3],
                        aT + SWZ((wm + mt * 16 + a_row) * 128 + ks * 32 + a_kb));
            #pragma unroll
            for (int nt = 0; nt < 4; nt++)
                ldsm_x2(b[nt][0], b[nt][1],
                        bT + SWZ((wn + nt * 8 + b_row) * 128 + ks * 32 + b_kb));
            #pragma unroll
            for (int mt = 0; mt < 4; mt++)
                #pragma unroll
                for (int nt = 0; nt < 4; nt++)
                    mma16816(acc[mt * 4 + nt], a[mt], b[nt]);
        }
    }

    // epilogue
    #pragma unroll
    for (int mt = 0; mt < 4; mt++) {
        #pragma unroll
        for (int nt = 0; nt < 4; nt++) {
            const float* d = acc[mt * 4 + nt];
            int row = tm + wm + mt * 16 + (lane >> 2);
            int col = tn + wn + nt * 8 + (lane & 3) * 2;
            if constexpr (sizeof(OutT) == 2) {
                *reinterpret_cast<__half2*>((__half*)C + (size_t)row * ldc + col)
                    = __floats2half2_rn(d[0], d[1]);
                *reinterpret_cast<__half2*>((__half*)C + (size_t)(row + 8) * ldc + col)
                    = __floats2half2_rn(d[2], d[3]);
            } else {
                *reinterpret_cast<float2*>((float*)C + (size_t)row * ldc + col)
                    = make_float2(d[0], d[1]);
                *reinterpret_cast<float2*>((float*)C + (size_t)(row + 8) * ldc + col)
                    = make_float2(d[2], d[3]);
            }
        }
    }
}

// ---------------- fused B*x -> causal conv(L=3) -> *C, fp16 in / fp16 out ------------
__global__ void __launch_bounds__(256) shortconv_kernel(const __half* __restrict__ BCx,
                                                        const float* __restrict__ cw,
                                                        __half* __restrict__ y) {
    int gid = blockIdx.x * 256 + threadIdx.x;  // 8192 * 512 threads
    int m = gid >> 9;
    int h = (gid & 511) * 4;
    int s = m & SEQMASK;

    const __half* row0 = BCx + (size_t)m * N1;
    auto ld4 = [](const __half* p, float* out) {
        uint2 u = *reinterpret_cast<const uint2*>(p);
        float2 lo = __half22float2(*reinterpret_cast<__half2*>(&u.x));
        float2 hi = __half22float2(*reinterpret_cast<__half2*>(&u.y));
        out[0] = lo.x; out[1] = lo.y; out[2] = hi.x; out[3] = hi.y;
    };

    float b0[4], cc[4], x0[4];
    float b1[4] = {0,0,0,0}, x1[4] = {0,0,0,0}, b2[4] = {0,0,0,0}, x2[4] = {0,0,0,0};
    ld4(row0 + h, b0);
    ld4(row0 + 2048 + h, cc);
    ld4(row0 + 4096 + h, x0);
    if (s >= 1) { ld4(row0 - N1 + h, b1); ld4(row0 - N1 + 4096 + h, x1); }
    if (s >= 2) { ld4(row0 - 2 * N1 + h, b2); ld4(row0 - 2 * N1 + 4096 + h, x2); }

    float out[4];
    #pragma unroll
    for (int j = 0; j < 4; j++) {
        float w0 = cw[(h + j) * 3 + 0];
        float w1 = cw[(h + j) * 3 + 1];
        float w2 = cw[(h + j) * 3 + 2];
        out[j] = cc[j] * (w0 * b2[j] * x2[j] + w1 * b1[j] * x1[j] + w2 * b0[j] * x0[j]);
    }
    *reinterpret_cast<__half2*>(y + (size_t)m * KDIM + h)     = __floats2half2_rn(out[0], out[1]);
    *reinterpret_cast<__half2*>(y + (size_t)m * KDIM + h + 2) = __floats2half2_rn(out[2], out[3]);
}

// ---------------- launch ----------------
extern "C" void kernel_launch(void* const* d_in, const int* in_sizes, int n_in,
                              void* d_out, int out_size) {
    const float* hs   = (const float*)d_in[0];
    const float* Win  = (const float*)d_in[1];
    const float* cw   = (const float*)d_in[2];
    const float* Wout = (const float*)d_in[3];
    float* out = (float*)d_out;

    void *pA, *pW1, *pW2, *pY, *pBCx;
    cudaGetSymbolAddress(&pA,  g_A);
    cudaGetSymbolAddress(&pW1, g_W1);
    cudaGetSymbolAddress(&pW2, g_W2);
    cudaGetSymbolAddress(&pY,  g_y);
    cudaGetSymbolAddress(&pBCx, g_BCx);

    cudaFuncSetAttribute(hgemm_tn<__half>, cudaFuncAttributeMaxDynamicSharedMemorySize, 98304);
    cudaFuncSetAttribute(hgemm_tn<float>,  cudaFuncAttributeMaxDynamicSharedMemorySize, 98304);

    convert_kernel<<<16384, 256>>>((const float4*)hs,   (uint2*)pA);
    convert_kernel<<<12288, 256>>>((const float4*)Win,  (uint2*)pW1);
    convert_kernel<<<4096,  256>>>((const float4*)Wout, (uint2*)pW2);

    // GEMM1: BCx[8192,6144] (fp16) = A * Win^T
    hgemm_tn<__half><<<dim3(N1 / 128, MDIM / 128), 256, 98304>>>(
        (const __half*)pA, (const __half*)pW1, (__half*)pBCx, N1);

    shortconv_kernel<<<(MDIM * KDIM / 4) / 256, 256>>>((const __half*)pBCx, cw, (__half*)pY);

    // GEMM2: out[8192,2048] (fp32) = y * Wout^T
    hgemm_tn<float><<<dim3(KDIM / 128, MDIM / 128), 256, 98304>>>(
        (const __half*)pY, (const __half*)pW2, out, KDIM);
}

// round 8
// speedup vs baseline: 1.6893x; 1.0734x over previous
#include <cuda_runtime.h>
#include <cuda_fp16.h>
#include <cstdint>
#include <cstddef>

// Sizes: hidden (2,4096,2048) f32; Win (6144,2048); conv_w (2048,1,3); Wout (2048,2048)
#define MDIM 8192
#define KDIM 2048
#define N1   6144
#define SEQMASK 4095
#define KT 32

// ---------------- device scratch ----------------
__device__ __half g_A  [MDIM * KDIM];          // 32 MB
__device__ __half g_W1 [N1   * KDIM];          // 24 MB
__device__ __half g_W2 [KDIM * KDIM];          // 8 MB
__device__ __half g_y  [MDIM * KDIM];          // 32 MB
__device__ __half g_BCx[(size_t)MDIM * N1];    // 96 MB fp16 GEMM1 output

// ---------------- helpers ----------------
__device__ __forceinline__ uint32_t smem_u32(const void* p) {
    uint32_t a;
    asm("{ .reg .u64 t; cvta.to.shared.u64 t, %1; cvt.u32.u64 %0, t; }" : "=r"(a) : "l"(p));
    return a;
}
__device__ __forceinline__ void cp16(uint32_t dst, const void* src) {
    asm volatile("cp.async.cg.shared.global [%0], [%1], 16;" :: "r"(dst), "l"(src));
}
__device__ __forceinline__ void ldsm_x4(uint32_t& r0, uint32_t& r1, uint32_t& r2, uint32_t& r3, uint32_t addr) {
    asm volatile("ldmatrix.sync.aligned.m8n8.x4.shared.b16 {%0,%1,%2,%3}, [%4];"
                 : "=r"(r0), "=r"(r1), "=r"(r2), "=r"(r3) : "r"(addr));
}
__device__ __forceinline__ void mma16816(float* d, const uint32_t* a, const uint32_t* b) {
    asm volatile(
        "mma.sync.aligned.m16n8k16.row.col.f32.f16.f16.f32 "
        "{%0,%1,%2,%3}, {%4,%5,%6,%7}, {%8,%9}, {%0,%1,%2,%3};"
        : "+f"(d[0]), "+f"(d[1]), "+f"(d[2]), "+f"(d[3])
        : "r"(a[0]), "r"(a[1]), "r"(a[2]), "r"(a[3]), "r"(b[0]), "r"(b[1]));
}

#define SWZ(o) ((o) ^ (((o) >> 3) & 0x70))

// ---------------- f32 -> f16 convert ----------------
__global__ void __launch_bounds__(256) convert_kernel(const float4* __restrict__ src,
                                                      uint2* __restrict__ dst) {
    int i = blockIdx.x * 256 + threadIdx.x;
    float4 v = src[i];
    __half2 a = __floats2half2_rn(v.x, v.y);
    __half2 b = __floats2half2_rn(v.z, v.w);
    uint2 u;
    u.x = *reinterpret_cast<unsigned*>(&a);
    u.y = *reinterpret_cast<unsigned*>(&b);
    dst[i] = u;
}

// ---------------- TN fp16 GEMM: C[M,N] = A[M,K] * W[N,K]^T ----------------
// BM=128, BN=256, BK=64 halfs (128B SW128 rows), 3 stages (144KB), 256 threads
// (8 warps 2m x 4n), warp tile 64x64 = 4x8 m16n8k16 frags. OutT selects epilogue type.
#define A_BYTES 16384              // 128 * 128B
#define B_BYTES 32768              // 256 * 128B
#define STAGE_BYTES (A_BYTES + B_BYTES)
#define GSMEM (3 * STAGE_BYTES)    // 147456

template <typename OutT>
__global__ void __launch_bounds__(256, 1) hgemm_tn(const __half* __restrict__ A,
                                                   const __half* __restrict__ W,
                                                   OutT* __restrict__ C, int ldc) {
    extern __shared__ char smem[];
    const int t = threadIdx.x;
    const int tm = blockIdx.y * 128;
    const int tn = blockIdx.x * 256;
    const uint32_t sb = smem_u32(smem);

    auto load_stage = [&](int st, int kt) {
        const uint32_t sa = sb + st * STAGE_BYTES;
        const __half* Ag = A + (size_t)tm * KDIM + kt * 64;
        const __half* Wg = W + (size_t)tn * KDIM + kt * 64;
        #pragma unroll
        for (int p = 0; p < 4; p++) {              // A: 1024 16B chunks
            int id = p * 256 + t;
            int r = id >> 3, c = id & 7;
            cp16(sa + SWZ(r * 128 + c * 16), Ag + (size_t)r * KDIM + c * 8);
        }
        #pragma unroll
        for (int p = 0; p < 8; p++) {              // B: 2048 16B chunks
            int id = p * 256 + t;
            int r = id >> 3, c = id & 7;
            cp16(sa + A_BYTES + SWZ(r * 128 + c * 16), Wg + (size_t)r * KDIM + c * 8);
        }
    };

    load_stage(0, 0); asm volatile("cp.async.commit_group;" ::: "memory");
    load_stage(1, 1); asm volatile("cp.async.commit_group;" ::: "memory");

    const int warp = t >> 5, lane = t & 31;
    const int wm = (warp >> 2) * 64;   // 2 warps in m
    const int wn = (warp & 3) * 64;    // 4 warps in n

    // A ldmatrix.x4 mapping (R2-proven): mats = (r0-7,k0),(r8-15,k0),(r0-7,k16B),(r8-15,k16B)
    const int g = lane >> 3;
    const int a_row = (g & 1) * 8 + (lane & 7);
    const int a_kb  = (g >> 1) * 16;
    // B ldmatrix.x4 mapping (R5-proven): mats = (n0-7,k0),(n0-7,k16B),(n8-15,k0),(n8-15,k16B)
    const int b_row = (lane >> 4) * 8 + (lane & 7);
    const int b_kb  = ((lane >> 3) & 1) * 16;

    float acc[32][4] = {};   // [mt*8 + nt][4]

    for (int kt = 0; kt < KT; kt++) {
        asm volatile("cp.async.wait_group 1;" ::: "memory");
        __syncthreads();
        if (kt + 2 < KT) load_stage((kt + 2) % 3, kt + 2);
        asm volatile("cp.async.commit_group;" ::: "memory");

        const uint32_t aT = sb + (kt % 3) * STAGE_BYTES;
        const uint32_t bT = aT + A_BYTES;
        #pragma unroll
        for (int ks = 0; ks < 4; ks++) {
            uint32_t a[4][4], b[8][2];
            #pragma unroll
            for (int mt = 0; mt < 4; mt++)
                ldsm_x4(a[mt][0], a[mt][1], a[mt][2], a[mt][3],
                        aT + SWZ((wm + mt * 16 + a_row) * 128 + ks * 32 + a_kb));
            #pragma unroll
            for (int nb = 0; nb < 4; nb++) {
                uint32_t r0, r1, r2, r3;
                ldsm_x4(r0, r1, r2, r3,
                        bT + SWZ((wn + nb * 16 + b_row) * 128 + ks * 32 + b_kb));
                b[nb * 2][0] = r0;     b[nb * 2][1] = r1;
                b[nb * 2 + 1][0] = r2; b[nb * 2 + 1][1] = r3;
            }
            #pragma unroll
            for (int mt = 0; mt < 4; mt++)
                #pragma unroll
                for (int nt = 0; nt < 8; nt++)
                    mma16816(acc[mt * 8 + nt], a[mt], b[nt]);
        }
    }

    // epilogue
    #pragma unroll
    for (int mt = 0; mt < 4; mt++) {
        #pragma unroll
        for (int nt = 0; nt < 8; nt++) {
            const float* d = acc[mt * 8 + nt];
            int row = tm + wm + mt * 16 + (lane >> 2);
            int col = tn + wn + nt * 8 + (lane & 3) * 2;
            if constexpr (sizeof(OutT) == 2) {
                *reinterpret_cast<__half2*>((__half*)C + (size_t)row * ldc + col)
                    = __floats2half2_rn(d[0], d[1]);
                *reinterpret_cast<__half2*>((__half*)C + (size_t)(row + 8) * ldc + col)
                    = __floats2half2_rn(d[2], d[3]);
            } else {
                *reinterpret_cast<float2*>((float*)C + (size_t)row * ldc + col)
                    = make_float2(d[0], d[1]);
                *reinterpret_cast<float2*>((float*)C + (size_t)(row + 8) * ldc + col)
                    = make_float2(d[2], d[3]);
            }
        }
    }
}

// ---------------- fused B*x -> causal conv(L=3) -> *C, fp16 in / fp16 out ------------
__global__ void __launch_bounds__(256) shortconv_kernel(const __half* __restrict__ BCx,
                                                        const float* __restrict__ cw,
                                                        __half* __restrict__ y) {
    int gid = blockIdx.x * 256 + threadIdx.x;
    int m = gid >> 9;
    int h = (gid & 511) * 4;
    int s = m & SEQMASK;

    const __half* row0 = BCx + (size_t)m * N1;
    auto ld4 = [](const __half* p, float* out) {
        uint2 u = *reinterpret_cast<const uint2*>(p);
        float2 lo = __half22float2(*reinterpret_cast<__half2*>(&u.x));
        float2 hi = __half22float2(*reinterpret_cast<__half2*>(&u.y));
        out[0] = lo.x; out[1] = lo.y; out[2] = hi.x; out[3] = hi.y;
    };

    float b0[4], cc[4], x0[4];
    float b1[4] = {0,0,0,0}, x1[4] = {0,0,0,0}, b2[4] = {0,0,0,0}, x2[4] = {0,0,0,0};
    ld4(row0 + h, b0);
    ld4(row0 + 2048 + h, cc);
    ld4(row0 + 4096 + h, x0);
    if (s >= 1) { ld4(row0 - N1 + h, b1); ld4(row0 - N1 + 4096 + h, x1); }
    if (s >= 2) { ld4(row0 - 2 * N1 + h, b2); ld4(row0 - 2 * N1 + 4096 + h, x2); }

    float out[4];
    #pragma unroll
    for (int j = 0; j < 4; j++) {
        float w0 = cw[(h + j) * 3 + 0];
        float w1 = cw[(h + j) * 3 + 1];
        float w2 = cw[(h + j) * 3 + 2];
        out[j] = cc[j] * (w0 * b2[j] * x2[j] + w1 * b1[j] * x1[j] + w2 * b0[j] * x0[j]);
    }
    *reinterpret_cast<__half2*>(y + (size_t)m * KDIM + h)     = __floats2half2_rn(out[0], out[1]);
    *reinterpret_cast<__half2*>(y + (size_t)m * KDIM + h + 2) = __floats2half2_rn(out[2], out[3]);
}

// ---------------- launch ----------------
extern "C" void kernel_launch(void* const* d_in, const int* in_sizes, int n_in,
                              void* d_out, int out_size) {
    const float* hs   = (const float*)d_in[0];
    const float* Win  = (const float*)d_in[1];
    const float* cw   = (const float*)d_in[2];
    const float* Wout = (const float*)d_in[3];
    float* out = (float*)d_out;

    void *pA, *pW1, *pW2, *pY, *pBCx;
    cudaGetSymbolAddress(&pA,  g_A);
    cudaGetSymbolAddress(&pW1, g_W1);
    cudaGetSymbolAddress(&pW2, g_W2);
    cudaGetSymbolAddress(&pY,  g_y);
    cudaGetSymbolAddress(&pBCx, g_BCx);

    cudaFuncSetAttribute(hgemm_tn<__half>, cudaFuncAttributeMaxDynamicSharedMemorySize, GSMEM);
    cudaFuncSetAttribute(hgemm_tn<float>,  cudaFuncAttributeMaxDynamicSharedMemorySize, GSMEM);

    convert_kernel<<<16384, 256>>>((const float4*)hs,   (uint2*)pA);
    convert_kernel<<<12288, 256>>>((const float4*)Win,  (uint2*)pW1);
    convert_kernel<<<4096,  256>>>((const float4*)Wout, (uint2*)pW2);

    // GEMM1: BCx[8192,6144] (fp16) = A * Win^T
    hgemm_tn<__half><<<dim3(N1 / 256, MDIM / 128), 256, GSMEM>>>(
        (const __half*)pA, (const __half*)pW1, (__half*)pBCx, N1);

    shortconv_kernel<<<(MDIM * KDIM / 4) / 256, 256>>>((const __half*)pBCx, cw, (__half*)pY);

    // GEMM2: out[8192,2048] (fp32) = y * Wout^T
    hgemm_tn<float><<<dim3(KDIM / 256, MDIM / 128), 256, GSMEM>>>(
        (const __half*)pY, (const __half*)pW2, out, KDIM);
}

// round 9
// speedup vs baseline: 2.0556x; 1.2169x over previous
#include <cuda_runtime.h>
#include <cuda_fp16.h>
#include <cstdint>
#include <cstddef>

// Sizes: hidden (2,4096,2048) f32; Win (6144,2048); conv_w (2048,1,3); Wout (2048,2048)
#define MDIM 8192
#define KDIM 2048
#define N1   6144
#define SEQMASK 4095
#define KT 32

// ---------------- device scratch ----------------
__device__ __half g_A  [MDIM * KDIM];          // 32 MB
__device__ __half g_W1 [N1   * KDIM];          // 24 MB
__device__ __half g_W2 [KDIM * KDIM];          // 8 MB
__device__ __half g_y  [MDIM * KDIM];          // 32 MB
__device__ __half g_BCx[(size_t)MDIM * N1];    // 96 MB fp16 GEMM1 output

// ---------------- helpers ----------------
__device__ __forceinline__ uint32_t smem_u32(const void* p) {
    uint32_t a;
    asm("{ .reg .u64 t; cvta.to.shared.u64 t, %1; cvt.u32.u64 %0, t; }" : "=r"(a) : "l"(p));
    return a;
}
__device__ __forceinline__ void cp16(uint32_t dst, const void* src) {
    asm volatile("cp.async.cg.shared.global [%0], [%1], 16;" :: "r"(dst), "l"(src));
}
__device__ __forceinline__ void ldsm_x4(uint32_t& r0, uint32_t& r1, uint32_t& r2, uint32_t& r3, uint32_t addr) {
    asm volatile("ldmatrix.sync.aligned.m8n8.x4.shared.b16 {%0,%1,%2,%3}, [%4];"
                 : "=r"(r0), "=r"(r1), "=r"(r2), "=r"(r3) : "r"(addr));
}
__device__ __forceinline__ void ldsm_x2(uint32_t& r0, uint32_t& r1, uint32_t addr) {
    asm volatile("ldmatrix.sync.aligned.m8n8.x2.shared.b16 {%0,%1}, [%2];"
                 : "=r"(r0), "=r"(r1) : "r"(addr));
}
__device__ __forceinline__ void mma16816(float* d, const uint32_t* a, const uint32_t* b) {
    asm volatile(
        "mma.sync.aligned.m16n8k16.row.col.f32.f16.f16.f32 "
        "{%0,%1,%2,%3}, {%4,%5,%6,%7}, {%8,%9}, {%0,%1,%2,%3};"
        : "+f"(d[0]), "+f"(d[1]), "+f"(d[2]), "+f"(d[3])
        : "r"(a[0]), "r"(a[1]), "r"(a[2]), "r"(a[3]), "r"(b[0]), "r"(b[1]));
}

#define SWZ(o) ((o) ^ (((o) >> 3) & 0x70))

// ---------------- f32 -> f16 convert ----------------
__global__ void __launch_bounds__(256) convert_kernel(const float4* __restrict__ src,
                                                      uint2* __restrict__ dst) {
    int i = blockIdx.x * 256 + threadIdx.x;
    float4 v = src[i];
    __half2 a = __floats2half2_rn(v.x, v.y);
    __half2 b = __floats2half2_rn(v.z, v.w);
    uint2 u;
    u.x = *reinterpret_cast<unsigned*>(&a);
    u.y = *reinterpret_cast<unsigned*>(&b);
    dst[i] = u;
}

// ---------------- TN fp16 GEMM (R4 frag-double-buffered config, 77.3% tensor) --------
// BM=BN=128, BK=64 halfs (128B SW128 rows), 4-stage cp.async ring, 256 threads
// (8 warps 2m x 4n, warp tile 64x32), double-buffered ldmatrix fragments.
#define STAGE_BYTES 32768          // A 16KB + B 16KB
#define GSMEM (4 * STAGE_BYTES)    // 131072

template <typename OutT>
__global__ void __launch_bounds__(256, 1) hgemm_tn(const __half* __restrict__ A,
                                                   const __half* __restrict__ W,
                                                   OutT* __restrict__ C, int ldc) {
    extern __shared__ char smem[];
    const int t = threadIdx.x;
    const int tm = blockIdx.y * 128;
    const int tn = blockIdx.x * 128;
    const uint32_t sb = smem_u32(smem);

    auto load_stage = [&](int st, int kt) {
        const uint32_t sa = sb + st * STAGE_BYTES;
        const __half* Ag = A + (size_t)tm * KDIM + kt * 64;
        const __half* Wg = W + (size_t)tn * KDIM + kt * 64;
        #pragma unroll
        for (int p = 0; p < 4; p++) {
            int id = p * 256 + t;
            int r = id >> 3, c = id & 7;
            cp16(sa + SWZ(r * 128 + c * 16), Ag + (size_t)r * KDIM + c * 8);
            cp16(sa + 16384 + SWZ(r * 128 + c * 16), Wg + (size_t)r * KDIM + c * 8);
        }
    };

    load_stage(0, 0); asm volatile("cp.async.commit_group;" ::: "memory");
    load_stage(1, 1); asm volatile("cp.async.commit_group;" ::: "memory");
    load_stage(2, 2); asm volatile("cp.async.commit_group;" ::: "memory");
    load_stage(3, 3); asm volatile("cp.async.commit_group;" ::: "memory");

    const int warp = t >> 5, lane = t & 31;
    const int wm = (warp >> 2) * 64;
    const int wn = (warp & 3) * 32;
    const int g = lane >> 3;
    const int a_row = (g & 1) * 8 + (lane & 7);
    const int a_kb  = (g >> 1) * 16;
    const int lg = lane & 15;
    const int b_row = lg & 7;
    const int b_kb  = (lg >> 3) * 16;

    const int axor = (a_row & 7) << 4;
    const int bxor = (b_row & 7) << 4;
    int rowA[4], rowB[4];
    #pragma unroll
    for (int mt = 0; mt < 4; mt++) rowA[mt] = (wm + mt * 16 + a_row) * 128;
    #pragma unroll
    for (int nt = 0; nt < 4; nt++) rowB[nt] = (wn + nt * 8 + b_row) * 128 + 16384;

    float acc[16][4] = {};
    uint32_t fa0[4][4], fa1[4][4], fb0[4][2], fb1[4][2];

#define LOAD_FRAGS(FA, FB, base, ksv)                                             \
    {                                                                             \
        const int ca = (((ksv) * 32 + a_kb) ^ axor);                              \
        const int cb = (((ksv) * 32 + b_kb) ^ bxor);                              \
        _Pragma("unroll")                                                         \
        for (int mt = 0; mt < 4; mt++)                                            \
            ldsm_x4(FA[mt][0], FA[mt][1], FA[mt][2], FA[mt][3], (base) + rowA[mt] + ca); \
        _Pragma("unroll")                                                         \
        for (int nt = 0; nt < 4; nt++)                                            \
            ldsm_x2(FB[nt][0], FB[nt][1], (base) + rowB[nt] + cb);                \
    }

#define MMA_STEP(FA, FB)                                                          \
    {                                                                             \
        _Pragma("unroll")                                                         \
        for (int mt = 0; mt < 4; mt++)                                            \
            _Pragma("unroll")                                                     \
            for (int nt = 0; nt < 4; nt++)                                        \
                mma16816(acc[mt * 4 + nt], FA[mt], FB[nt]);                       \
    }

    asm volatile("cp.async.wait_group 3;" ::: "memory");
    __syncthreads();
    LOAD_FRAGS(fa0, fb0, sb, 0);

    for (int kt = 0; kt < KT; kt++) {
        const uint32_t sc = sb + (kt & 3) * STAGE_BYTES;
        LOAD_FRAGS(fa1, fb1, sc, 1);
        MMA_STEP(fa0, fb0);
        LOAD_FRAGS(fa0, fb0, sc, 2);
        MMA_STEP(fa1, fb1);
        LOAD_FRAGS(fa1, fb1, sc, 3);
        MMA_STEP(fa0, fb0);
        MMA_STEP(fa1, fb1);

        __syncthreads();                       // all warps done reading slot kt&3
        if (kt + 4 < KT) load_stage(kt & 3, kt + 4);
        asm volatile("cp.async.commit_group;" ::: "memory");
        asm volatile("cp.async.wait_group 3;" ::: "memory");
        __syncthreads();                       // stage kt+1 visible
        if (kt + 1 < KT) {
            const uint32_t sn = sb + ((kt + 1) & 3) * STAGE_BYTES;
            LOAD_FRAGS(fa0, fb0, sn, 0);
        }
    }

    // epilogue
    #pragma unroll
    for (int mt = 0; mt < 4; mt++) {
        #pragma unroll
        for (int nt = 0; nt < 4; nt++) {
            const float* d = acc[mt * 4 + nt];
            int row = tm + wm + mt * 16 + (lane >> 2);
            int col = tn + wn + nt * 8 + (lane & 3) * 2;
            if constexpr (sizeof(OutT) == 2) {
                *reinterpret_cast<__half2*>((__half*)C + (size_t)row * ldc + col)
                    = __floats2half2_rn(d[0], d[1]);
                *reinterpret_cast<__half2*>((__half*)C + (size_t)(row + 8) * ldc + col)
                    = __floats2half2_rn(d[2], d[3]);
            } else {
                *reinterpret_cast<float2*>((float*)C + (size_t)row * ldc + col)
                    = make_float2(d[0], d[1]);
                *reinterpret_cast<float2*>((float*)C + (size_t)(row + 8) * ldc + col)
                    = make_float2(d[2], d[3]);
            }
        }
    }
#undef LOAD_FRAGS
#undef MMA_STEP
}

// ---------------- fused B*x -> causal conv(L=3) -> *C, fp16 in / fp16 out ------------
__global__ void __launch_bounds__(256) shortconv_kernel(const __half* __restrict__ BCx,
                                                        const float* __restrict__ cw,
                                                        __half* __restrict__ y) {
    int gid = blockIdx.x * 256 + threadIdx.x;
    int m = gid >> 9;
    int h = (gid & 511) * 4;
    int s = m & SEQMASK;

    const __half* row0 = BCx + (size_t)m * N1;
    auto ld4 = [](const __half* p, float* out) {
        uint2 u = *reinterpret_cast<const uint2*>(p);
        float2 lo = __half22float2(*reinterpret_cast<__half2*>(&u.x));
        float2 hi = __half22float2(*reinterpret_cast<__half2*>(&u.y));
        out[0] = lo.x; out[1] = lo.y; out[2] = hi.x; out[3] = hi.y;
    };

    float b0[4], cc[4], x0[4];
    float b1[4] = {0,0,0,0}, x1[4] = {0,0,0,0}, b2[4] = {0,0,0,0}, x2[4] = {0,0,0,0};
    ld4(row0 + h, b0);
    ld4(row0 + 2048 + h, cc);
    ld4(row0 + 4096 + h, x0);
    if (s >= 1) { ld4(row0 - N1 + h, b1); ld4(row0 - N1 + 4096 + h, x1); }
    if (s >= 2) { ld4(row0 - 2 * N1 + h, b2); ld4(row0 - 2 * N1 + 4096 + h, x2); }

    float out[4];
    #pragma unroll
    for (int j = 0; j < 4; j++) {
        float w0 = cw[(h + j) * 3 + 0];
        float w1 = cw[(h + j) * 3 + 1];
        float w2 = cw[(h + j) * 3 + 2];
        out[j] = cc[j] * (w0 * b2[j] * x2[j] + w1 * b1[j] * x1[j] + w2 * b0[j] * x0[j]);
    }
    *reinterpret_cast<__half2*>(y + (size_t)m * KDIM + h)     = __floats2half2_rn(out[0], out[1]);
    *reinterpret_cast<__half2*>(y + (size_t)m * KDIM + h + 2) = __floats2half2_rn(out[2], out[3]);
}

// ---------------- launch ----------------
extern "C" void kernel_launch(void* const* d_in, const int* in_sizes, int n_in,
                              void* d_out, int out_size) {
    const float* hs   = (const float*)d_in[0];
    const float* Win  = (const float*)d_in[1];
    const float* cw   = (const float*)d_in[2];
    const float* Wout = (const float*)d_in[3];
    float* out = (float*)d_out;

    void *pA, *pW1, *pW2, *pY, *pBCx;
    cudaGetSymbolAddress(&pA,  g_A);
    cudaGetSymbolAddress(&pW1, g_W1);
    cudaGetSymbolAddress(&pW2, g_W2);
    cudaGetSymbolAddress(&pY,  g_y);
    cudaGetSymbolAddress(&pBCx, g_BCx);

    cudaFuncSetAttribute(hgemm_tn<__half>, cudaFuncAttributeMaxDynamicSharedMemorySize, GSMEM);
    cudaFuncSetAttribute(hgemm_tn<float>,  cudaFuncAttributeMaxDynamicSharedMemorySize, GSMEM);

    convert_kernel<<<16384, 256>>>((const float4*)hs,   (uint2*)pA);
    convert_kernel<<<12288, 256>>>((const float4*)Win,  (uint2*)pW1);
    convert_kernel<<<4096,  256>>>((const float4*)Wout, (uint2*)pW2);

    // GEMM1: BCx[8192,6144] (fp16) = A * Win^T
    hgemm_tn<__half><<<dim3(N1 / 128, MDIM / 128), 256, GSMEM>>>(
        (const __half*)pA, (const __half*)pW1, (__half*)pBCx, N1);

    shortconv_kernel<<<(MDIM * KDIM / 4) / 256, 256>>>((const __half*)pBCx, cw, (__half*)pY);

    // GEMM2: out[8192,2048] (fp32) = y * Wout^T
    hgemm_tn<float><<<dim3(KDIM / 128, MDIM / 128), 256, GSMEM>>>(
        (const __half*)pY, (const __half*)pW2, out, KDIM);
}